// round 14
// baseline (speedup 1.0000x reference)
#include <cuda_runtime.h>
#include <cuda_fp16.h>
#include <math.h>
#include <stdint.h>

// Problem constants
#define B_   16
#define H_   64
#define W_   64
#define C_   512
#define NH_  16
#define HD_  32
#define NTOK 65536
#define NWIN 64
#define NROW 65536

// ---------------- device scratch (allocation-free) ----------------
__device__ float g_xw[(size_t)NROW * C_];    // half activations (u32-packed), reused
__device__ float g_q [(size_t)NROW * C_];    // fp32 proj-out / fc2-out
__device__ float g_v [(size_t)NROW * C_];    // fp32 x1
__device__ float g_h [(size_t)NROW * 2048];  // qkv half (front) + mlp hidden half
__device__ float g_wr[3145728];              // k-pair packed half weights (u32 view)
__device__ float g_tbl[225 * 16];
__device__ float g_qkvb[1536];

// ---------------- helpers ----------------
__device__ __forceinline__ uint32_t smem_u32(const void* p) {
    uint32_t a;
    asm("{ .reg .u64 t; cvta.to.shared.u64 t, %1; cvt.u32.u64 %0, t; }" : "=r"(a) : "l"(p));
    return a;
}
__device__ __forceinline__ uint32_t packh2(float lo, float hi) {
    __half2 h = __floats2half2_rn(lo, hi);
    return *reinterpret_cast<uint32_t*>(&h);
}
__device__ __forceinline__ void cp16r(uint32_t saddr, const void* gsrc) {
    asm volatile("cp.async.cg.shared.global [%0], [%1], 16;" :: "r"(saddr), "l"(gsrc) : "memory");
}
#define CP_COMMIT() asm volatile("cp.async.commit_group;" ::: "memory")
#define CP_WAIT1()  asm volatile("cp.async.wait_group 1;" ::: "memory")

__device__ __forceinline__ void ldsm4(const void* p, uint32_t* r) {
    uint32_t a = smem_u32(p);
    asm volatile("ldmatrix.sync.aligned.m8n8.x4.shared.b16 {%0,%1,%2,%3}, [%4];"
        : "=r"(r[0]), "=r"(r[1]), "=r"(r[2]), "=r"(r[3]) : "r"(a));
}
__device__ __forceinline__ void mma_f16(float* c, uint32_t a0, uint32_t a1,
                                        uint32_t a2, uint32_t a3,
                                        uint32_t b0, uint32_t b1) {
    asm volatile(
        "mma.sync.aligned.m16n8k16.row.col.f32.f16.f16.f32 "
        "{%0,%1,%2,%3}, {%4,%5,%6,%7}, {%8,%9}, {%0,%1,%2,%3};"
        : "+f"(c[0]), "+f"(c[1]), "+f"(c[2]), "+f"(c[3])
        : "r"(a0), "r"(a1), "r"(a2), "r"(a3), "r"(b0), "r"(b1));
}
__device__ __forceinline__ float gelu_f(float t) {
    return 0.5f * t * (1.0f + tanhf(0.7978845608028654f * (t + 0.044715f * t * t * t)));
}

// ---------------- merged prep: weights f32 -> k-pair half2 layout -----------
// dst u32 layout [K/2][dstN]: u32 at (kp, c) = half2(src[2kp][c], src[2kp+1][c])
__device__ __forceinline__ void pack_one(const float* __restrict__ src, uint32_t* __restrict__ dst,
                                         int N, int dstN, int coloff, int local)
{
    int n4c = N >> 2;
    int kp = local / n4c, n4 = local % n4c;
    float4 r0 = ((const float4*)(src + (size_t)(2 * kp) * N))[n4];
    float4 r1 = ((const float4*)(src + (size_t)(2 * kp + 1) * N))[n4];
    uint4 u;
    u.x = packh2(r0.x, r1.x);
    u.y = packh2(r0.y, r1.y);
    u.z = packh2(r0.z, r1.z);
    u.w = packh2(r0.w, r1.w);
    *(uint4*)(dst + (size_t)kp * dstN + coloff + (n4 << 2)) = u;
}

__global__ void pack_all(const float* __restrict__ q_w, const float* __restrict__ k_w,
                         const float* __restrict__ v_w, const float* __restrict__ p_w,
                         const float* __restrict__ w1, const float* __restrict__ w2,
                         const float* __restrict__ qb, const float* __restrict__ vb,
                         uint32_t* __restrict__ wqkv, uint32_t* __restrict__ wp,
                         uint32_t* __restrict__ wf1, uint32_t* __restrict__ wf2,
                         float* __restrict__ qkvb)
{
    int idx = blockIdx.x * 256 + threadIdx.x;
    if (idx < 32768)        pack_one(q_w, wqkv, 512, 1536, 0,    idx);
    else if (idx < 65536)   pack_one(k_w, wqkv, 512, 1536, 512,  idx - 32768);
    else if (idx < 98304)   pack_one(v_w, wqkv, 512, 1536, 1024, idx - 65536);
    else if (idx < 131072)  pack_one(p_w, wp,   512, 512, 0,     idx - 98304);
    else if (idx < 262144)  pack_one(w1,  wf1, 2048, 2048, 0,    idx - 131072);
    else if (idx < 393216)  pack_one(w2,  wf2,  512, 512, 0,     idx - 262144);
    else if (idx < 394752) {
        int i = idx - 393216;
        float v = 0.0f;
        if (i < 512) v = qb[i];
        else if (i >= 1024) v = vb[i - 1024];
        qkvb[i] = v;
    }
}

// ---------------- fp16 mma.sync GEMM: A smem + direct-LDG B fragments -------
// C[M,N] = A[M,K]*B[K,N]. A: half [M][K] (u32 view). B: k-pair [K/2][N] u32.
// CTA 128x128, 8 warps (2x4 -> 64x32), K-chunk 64, 3 A-stages, 2 CTAs/SM.
#define AS_U 36                       // u32 per A smem row (32 data + 4 pad)
#define SA_U (128 * AS_U)             // 4608 u32 per stage
#define STG_U SA_U
#define STG_B (STG_U * 4)             // 18432 B
#define GEMM_SMEM (3 * STG_B)         // 55296 B
#define ARB (32 * AS_U * 4)

template<int GELU, int HALF_OUT>
__global__ void __launch_bounds__(256, 2) mma_gemm(
    const uint32_t* __restrict__ A, const uint32_t* __restrict__ B,
    const float* __restrict__ bias, void* __restrict__ Cv,
    int N, int K)
{
    extern __shared__ uint32_t smem[];
    const uint32_t sbase = smem_u32(smem);
    const int tid = threadIdx.x;
    const int wid = tid >> 5, lane = tid & 31;
    const int g = lane >> 2, t = lane & 3;
    const int lq = lane & 15, lh = lane >> 4;
    const int wm = wid >> 2, wn = wid & 3;
    const int mw = wm * 64, nw = wn * 32;
    const int m0 = blockIdx.y * 128, n0 = blockIdx.x * 128;
    const int K2 = K >> 1;

    // A staging (pointer induction)
    const uint32_t* aptr = A + (size_t)(m0 + (tid >> 3)) * K2 + ((tid & 7) << 2);
    const size_t aRow = (size_t)32 * K2;
    const uint32_t saA = sbase + ((tid >> 3) * AS_U + ((tid & 7) << 2)) * 4;

#define STAGEA(soff) do { \
    cp16r(saA + (soff),           aptr); \
    cp16r(saA + (soff) + ARB,     aptr + aRow); \
    cp16r(saA + (soff) + 2 * ARB, aptr + 2 * aRow); \
    cp16r(saA + (soff) + 3 * ARB, aptr + 3 * aRow); \
    aptr += 32; } while (0)

    // B fragment rolling pointer: row = k-pair index, starts at t
    const uint32_t* bp = B + (size_t)t * N + n0 + nw + (lane >> 2);
    const size_t bKs = (size_t)8 * N;       // advance 8 k-pairs per k16 step

    float acc[4][4][4];
#pragma unroll
    for (int i = 0; i < 4; i++)
#pragma unroll
        for (int j = 0; j < 4; j++)
#pragma unroll
            for (int q = 0; q < 4; q++) acc[i][j][q] = 0.0f;

    const int nch = K >> 6;

    STAGEA(0);        CP_COMMIT();
    STAGEA(STG_B);    CP_COMMIT();

    int curU = 0;
    int prevB = 2 * STG_B;

    for (int ch = 0; ch < nch; ++ch) {
        // issue ALL B fragment loads for this chunk BEFORE waiting on A:
        // latency hides under cp.async wait + barrier + A staging.
        uint32_t bf[4][8];
#pragma unroll
        for (int ks = 0; ks < 4; ++ks) {
#pragma unroll
            for (int nf = 0; nf < 4; ++nf) {
                bf[ks][nf * 2]     = bp[nf * 8];
                bf[ks][nf * 2 + 1] = bp[4 * (size_t)N + nf * 8];
            }
            bp += bKs;
        }

        CP_WAIT1();
        __syncthreads();
        if (ch + 2 < nch) STAGEA(prevB);
        CP_COMMIT();

        const uint32_t* As = smem + curU;
#pragma unroll
        for (int ks = 0; ks < 4; ++ks) {
#pragma unroll
            for (int mf = 0; mf < 4; ++mf) {
                uint32_t af[4];
                ldsm4(&As[(mw + mf * 16 + lq) * AS_U + ks * 8 + (lh << 2)], af);
#pragma unroll
                for (int nf = 0; nf < 4; ++nf)
                    mma_f16(acc[mf][nf], af[0], af[1], af[2], af[3],
                            bf[ks][nf * 2], bf[ks][nf * 2 + 1]);
            }
        }

        prevB = curU * 4;
        curU = (curU == 2 * STG_U) ? 0 : curU + STG_U;
    }
#undef STAGEA

    // epilogue
#pragma unroll
    for (int mf = 0; mf < 4; ++mf) {
        const int row = m0 + mw + mf * 16 + g;
#pragma unroll
        for (int nf = 0; nf < 4; ++nf) {
            const int col = n0 + nw + nf * 8 + t * 2;
            float b0 = 0.f, b1 = 0.f;
            if (bias) { b0 = bias[col]; b1 = bias[col + 1]; }
            float c0 = acc[mf][nf][0] + b0, c1 = acc[mf][nf][1] + b1;
            float c2 = acc[mf][nf][2] + b0, c3 = acc[mf][nf][3] + b1;
            if (GELU) { c0 = gelu_f(c0); c1 = gelu_f(c1); c2 = gelu_f(c2); c3 = gelu_f(c3); }
            if (HALF_OUT) {
                uint32_t* Ch = (uint32_t*)Cv;
                Ch[((size_t)row * N + col) >> 1]       = packh2(c0, c1);
                Ch[((size_t)(row + 8) * N + col) >> 1] = packh2(c2, c3);
            } else {
                float* Cf = (float*)Cv;
                *(float2*)(Cf + (size_t)row * N + col)       = make_float2(c0, c1);
                *(float2*)(Cf + (size_t)(row + 8) * N + col) = make_float2(c2, c3);
            }
        }
    }
}

// ---------------- CPB bias table ----------------
__global__ void cpb_kernel(const float* __restrict__ w1, const float* __restrict__ b1,
                           const float* __restrict__ w2, const float* __restrict__ b2,
                           float* __restrict__ tbl)
{
    int f = blockIdx.x;
    int h = threadIdx.x;
    int i = f / 15, j = f % 15;
    float v0 = 8.0f * (float)(j - 7) / 7.0f;
    float v1 = 8.0f * (float)(i - 7) / 7.0f;
    float c0 = copysignf(log2f(fabsf(v0) + 1.0f) * (1.0f / 3.0f), v0);
    float c1 = copysignf(log2f(fabsf(v1) + 1.0f) * (1.0f / 3.0f), v1);
    float hid = fmaxf(c0 * w1[h] + c1 * w1[512 + h] + b1[h], 0.0f);

    __shared__ float red[512];
    for (int nh = 0; nh < 16; ++nh) {
        red[h] = hid * w2[h * 16 + nh];
        __syncthreads();
        for (int s = 256; s > 0; s >>= 1) {
            if (h < s) red[h] += red[h + s];
            __syncthreads();
        }
        if (h == 0) tbl[f * 16 + nh] = red[0] + b2[nh];
        __syncthreads();
    }
}

// ---------------- shift + window partition gather -> half -------------------
__global__ void gather_xw(const float* __restrict__ x, uint32_t* __restrict__ xw)
{
    size_t idx = (size_t)blockIdx.x * 256 + threadIdx.x;
    if (idx >= (size_t)NROW * 128) return;
    int c4  = (int)(idx & 127);
    int row = (int)(idx >> 7);
    int n = row & 63, bw = row >> 6;
    int win = bw & 63, b = bw >> 6;
    int wh = win >> 3, wwn = win & 7;
    int i = n >> 3, j = n & 7;
    int h = ((wh << 3) + i + 4) & 63;
    int w = ((wwn << 3) + j + 4) & 63;
    float4 vv = *(((const float4*)(x + (size_t)((b << 12) + (h << 6) + w) * C_)) + c4);
    uint2 u;
    u.x = packh2(vv.x, vv.y);
    u.y = packh2(vv.z, vv.w);
    *(uint2*)(xw + (size_t)row * 256 + c4 * 2) = u;
}

// ---------------- tensor-core windowed cosine attention ---------------------
__global__ void __launch_bounds__(128) attn_tc(
    const uint32_t* __restrict__ qkv,
    const float* __restrict__ tau, const float* __restrict__ tbl,
    uint32_t* __restrict__ out)
{
    __shared__ uint32_t Qh[64 * 17];
    __shared__ uint32_t Kh[64 * 17];
    __shared__ __half sVt[32 * 72];
    __shared__ float qn[64], kn[64];

    const int blk = blockIdx.x;
    const int head = blk & 15, bw = blk >> 4;
    const int win = bw & 63;
    const int tid = threadIdx.x;
    const int wid = tid >> 5, lane = tid & 31;
    const int g = lane >> 2, t = lane & 3;
    const int mr = wid << 4;

    const uint32_t* base = qkv + (size_t)(bw << 6) * 768 + (head << 4);

    for (int i = tid; i < 1024; i += 128) {
        int tok = i >> 4, c = i & 15;
        Qh[tok * 17 + c] = base[(size_t)tok * 768 + c];
        Kh[tok * 17 + c] = base[(size_t)tok * 768 + 256 + c];
    }
    for (int i = tid; i < 1024; i += 128) {
        int tok = i >> 4, dp = i & 15;
        uint32_t u = base[(size_t)tok * 768 + 512 + dp];
        __half2 h = *(__half2*)&u;
        sVt[(dp * 2) * 72 + tok]     = __low2half(h);
        sVt[(dp * 2 + 1) * 72 + tok] = __high2half(h);
    }
    __syncthreads();

    {
        int tok = tid & 63;
        const uint32_t* src = (tid < 64) ? &Qh[tok * 17] : &Kh[tok * 17];
        float s = 0.0f;
#pragma unroll
        for (int c = 0; c < 16; ++c) {
            float2 f = __half22float2(*(__half2*)&src[c]);
            s = fmaf(f.x, f.x, fmaf(f.y, f.y, s));
        }
        if (tid < 64) qn[tok] = sqrtf(s); else kn[tok] = sqrtf(s);
    }
    __syncthreads();

    float sacc[8][4];
#pragma unroll
    for (int nf = 0; nf < 8; ++nf)
#pragma unroll
        for (int e = 0; e < 4; ++e) sacc[nf][e] = 0.0f;

    uint32_t aq[2][4];
#pragma unroll
    for (int kb = 0; kb < 2; ++kb) {
        aq[kb][0] = Qh[(mr + g) * 17 + kb * 8 + t];
        aq[kb][1] = Qh[(mr + g + 8) * 17 + kb * 8 + t];
        aq[kb][2] = Qh[(mr + g) * 17 + kb * 8 + t + 4];
        aq[kb][3] = Qh[(mr + g + 8) * 17 + kb * 8 + t + 4];
    }
#pragma unroll
    for (int nf = 0; nf < 8; ++nf) {
        const int col = (nf << 3) + g;
#pragma unroll
        for (int kb = 0; kb < 2; ++kb) {
            uint32_t b0 = Kh[col * 17 + kb * 8 + t];
            uint32_t b1 = Kh[col * 17 + kb * 8 + t + 4];
            mma_f16(sacc[nf], aq[kb][0], aq[kb][1], aq[kb][2], aq[kb][3], b0, b1);
        }
    }

    const float ls = fmaxf(tau[head] + 2.302585092994046f, 0.01f);
    const int whb = (win >> 3) << 3, wwb = (win & 7) << 3;
    const int r1 = mr + g, r2 = mr + g + 8;
    float mx1 = -1e30f, mx2 = -1e30f;
#pragma unroll
    for (int nf = 0; nf < 8; ++nf) {
#pragma unroll
        for (int e = 0; e < 4; ++e) {
            const int r = (e < 2) ? r1 : r2;
            const int c = (nf << 3) + (t << 1) + (e & 1);
            float a = sacc[nf][e] / fmaxf(qn[r] * kn[c], 1e-6f) * ls;
            int dr = (r >> 3) - (c >> 3), dc = (r & 7) - (c & 7);
            float bsv = tbl[((dr + 7) * 15 + (dc + 7)) * 16 + head];
            a += 16.0f / (1.0f + expf(-bsv));
            int hn = whb + (r >> 3), wn = wwb + (r & 7);
            int hm = whb + (c >> 3), wm = wwb + (c & 7);
            int rn = (hn < 56 ? 0 : (hn < 60 ? 1 : 2)) * 3 + (wn < 56 ? 0 : (wn < 60 ? 1 : 2));
            int rm = (hm < 56 ? 0 : (hm < 60 ? 1 : 2)) * 3 + (wm < 56 ? 0 : (wm < 60 ? 1 : 2));
            if (rn != rm) a -= 100.0f;
            sacc[nf][e] = a;
            if (e < 2) mx1 = fmaxf(mx1, a); else mx2 = fmaxf(mx2, a);
        }
    }
#pragma unroll
    for (int o = 1; o <= 2; o <<= 1) {
        mx1 = fmaxf(mx1, __shfl_xor_sync(0xffffffffu, mx1, o));
        mx2 = fmaxf(mx2, __shfl_xor_sync(0xffffffffu, mx2, o));
    }
    float s1 = 0.0f, s2 = 0.0f;
#pragma unroll
    for (int nf = 0; nf < 8; ++nf) {
        float e0 = expf(sacc[nf][0] - mx1);
        float e1 = expf(sacc[nf][1] - mx1);
        float e2 = expf(sacc[nf][2] - mx2);
        float e3 = expf(sacc[nf][3] - mx2);
        sacc[nf][0] = e0; sacc[nf][1] = e1; sacc[nf][2] = e2; sacc[nf][3] = e3;
        s1 += e0 + e1; s2 += e2 + e3;
    }
#pragma unroll
    for (int o = 1; o <= 2; o <<= 1) {
        s1 += __shfl_xor_sync(0xffffffffu, s1, o);
        s2 += __shfl_xor_sync(0xffffffffu, s2, o);
    }
    const float inv1 = 1.0f / s1, inv2 = 1.0f / s2;

    float oacc[4][4];
#pragma unroll
    for (int nf = 0; nf < 4; ++nf)
#pragma unroll
        for (int e = 0; e < 4; ++e) oacc[nf][e] = 0.0f;

    const uint32_t* vt32 = (const uint32_t*)sVt;
#pragma unroll
    for (int kc = 0; kc < 4; ++kc) {
        uint32_t a0 = packh2(sacc[kc * 2][0],     sacc[kc * 2][1]);
        uint32_t a1 = packh2(sacc[kc * 2][2],     sacc[kc * 2][3]);
        uint32_t a2 = packh2(sacc[kc * 2 + 1][0], sacc[kc * 2 + 1][1]);
        uint32_t a3 = packh2(sacc[kc * 2 + 1][2], sacc[kc * 2 + 1][3]);
#pragma unroll
        for (int nf = 0; nf < 4; ++nf) {
            const int d = (nf << 3) + g;
            uint32_t b0 = vt32[d * 36 + kc * 8 + t];
            uint32_t b1 = vt32[d * 36 + kc * 8 + t + 4];
            mma_f16(oacc[nf], a0, a1, a2, a3, b0, b1);
        }
    }

    const size_t orow1 = (size_t)((bw << 6) + r1) * 256 + (head << 4);
    const size_t orow2 = (size_t)((bw << 6) + r2) * 256 + (head << 4);
#pragma unroll
    for (int nf = 0; nf < 4; ++nf) {
        out[orow1 + (nf << 2) + t] = packh2(oacc[nf][0] * inv1, oacc[nf][1] * inv1);
        out[orow2 + (nf << 2) + t] = packh2(oacc[nf][2] * inv2, oacc[nf][3] * inv2);
    }
}

// ---------------- (optional gather) + LayerNorm + residual ----------------
__global__ void __launch_bounds__(128) ln_res_kernel(
    const float* __restrict__ src, const float* __restrict__ resid,
    const float* __restrict__ g, const float* __restrict__ bb,
    float* __restrict__ dst, uint32_t* __restrict__ dst_half, int gather)
{
    int r = blockIdx.x, tid = threadIdx.x;
    int srow = r;
    if (gather) {
        int b = r >> 12, hw = r & 4095;
        int h = hw >> 6, w = hw & 63;
        int hh = (h + 60) & 63, wv = (w + 60) & 63;
        srow = (((b << 6) + ((hh >> 3) << 3) + (wv >> 3)) << 6) + ((hh & 7) << 3) + (wv & 7);
    }
    float4 val = ((const float4*)(src + (size_t)srow * C_))[tid];
    __shared__ float sh[4];

    float s = val.x + val.y + val.z + val.w;
#pragma unroll
    for (int o = 16; o; o >>= 1) s += __shfl_xor_sync(0xffffffffu, s, o);
    if ((tid & 31) == 0) sh[tid >> 5] = s;
    __syncthreads();
    float mean = (sh[0] + sh[1] + sh[2] + sh[3]) * (1.0f / 512.0f);
    __syncthreads();

    float dx = val.x - mean, dy = val.y - mean, dz = val.z - mean, dw = val.w - mean;
    float s2 = dx * dx + dy * dy + dz * dz + dw * dw;
#pragma unroll
    for (int o = 16; o; o >>= 1) s2 += __shfl_xor_sync(0xffffffffu, s2, o);
    if ((tid & 31) == 0) sh[tid >> 5] = s2;
    __syncthreads();
    float var = (sh[0] + sh[1] + sh[2] + sh[3]) * (1.0f / 512.0f);
    float rstd = rsqrtf(var + 1e-6f);

    float4 gg = ((const float4*)g)[tid];
    float4 bv = ((const float4*)bb)[tid];
    float4 xr = ((const float4*)(resid + (size_t)r * C_))[tid];
    float4 o;
    o.x = xr.x + dx * rstd * gg.x + bv.x;
    o.y = xr.y + dy * rstd * gg.y + bv.y;
    o.z = xr.z + dz * rstd * gg.z + bv.z;
    o.w = xr.w + dw * rstd * gg.w + bv.w;
    ((float4*)(dst + (size_t)r * C_))[tid] = o;
    if (dst_half) {
        uint2 u;
        u.x = packh2(o.x, o.y);
        u.y = packh2(o.z, o.w);
        *(uint2*)(dst_half + (size_t)r * 256 + tid * 2) = u;
    }
}

// ---------------- host launch ----------------
extern "C" void kernel_launch(void* const* d_in, const int* in_sizes, int n_in,
                              void* d_out, int out_size)
{
    const float* x      = (const float*)d_in[0];
    const float* q_w    = (const float*)d_in[1];
    const float* q_b    = (const float*)d_in[2];
    const float* k_w    = (const float*)d_in[3];
    const float* v_w    = (const float*)d_in[4];
    const float* v_b    = (const float*)d_in[5];
    const float* proj_w = (const float*)d_in[6];
    const float* proj_b = (const float*)d_in[7];
    const float* tau    = (const float*)d_in[8];
    const float* cpb_w1 = (const float*)d_in[9];
    const float* cpb_b1 = (const float*)d_in[10];
    const float* cpb_w2 = (const float*)d_in[11];
    const float* cpb_b2 = (const float*)d_in[12];
    const float* n1g    = (const float*)d_in[13];
    const float* n1b    = (const float*)d_in[14];
    const float* n2g    = (const float*)d_in[15];
    const float* n2b    = (const float*)d_in[16];
    const float* w1     = (const float*)d_in[17];
    const float* b1     = (const float*)d_in[18];
    const float* w2     = (const float*)d_in[19];
    const float* b2     = (const float*)d_in[20];
    float* out = (float*)d_out;

    float *xwf, *q, *v, *hf, *wrf, *tbl, *qkvb;
    cudaGetSymbolAddress((void**)&xwf,  g_xw);
    cudaGetSymbolAddress((void**)&q,    g_q);
    cudaGetSymbolAddress((void**)&v,    g_v);
    cudaGetSymbolAddress((void**)&hf,   g_h);
    cudaGetSymbolAddress((void**)&wrf,  g_wr);
    cudaGetSymbolAddress((void**)&tbl,  g_tbl);
    cudaGetSymbolAddress((void**)&qkvb, g_qkvb);

    uint32_t* xw   = (uint32_t*)xwf;
    uint32_t* qkvh = (uint32_t*)hf;
    uint32_t* hb   = (uint32_t*)(hf + 50331648);
    uint32_t* wr   = (uint32_t*)wrf;

    uint32_t* wqkv = wr;                 // [256][1536] u32
    uint32_t* wp   = wr + 393216;        // [256][512]
    uint32_t* wf1  = wr + 524288;        // [256][2048]
    uint32_t* wf2  = wr + 1048576;       // [1024][512]

    cudaFuncSetAttribute((const void*)mma_gemm<0, 0>,
                         cudaFuncAttributeMaxDynamicSharedMemorySize, GEMM_SMEM);
    cudaFuncSetAttribute((const void*)mma_gemm<0, 1>,
                         cudaFuncAttributeMaxDynamicSharedMemorySize, GEMM_SMEM);
    cudaFuncSetAttribute((const void*)mma_gemm<1, 1>,
                         cudaFuncAttributeMaxDynamicSharedMemorySize, GEMM_SMEM);

    pack_all<<<1542, 256>>>(q_w, k_w, v_w, proj_w, w1, w2, q_b, v_b,
                            wqkv, wp, wf1, wf2, qkvb);
    cpb_kernel<<<225, 512>>>(cpb_w1, cpb_b1, cpb_w2, cpb_b2, tbl);
    gather_xw<<<(NROW * 128) / 256, 256>>>(x, xw);

    mma_gemm<0, 1><<<dim3(12, 512), 256, GEMM_SMEM>>>(xw, wqkv, qkvb, qkvh, 1536, 512);
    attn_tc<<<16384, 128>>>(qkvh, tau, tbl, xw);
    mma_gemm<0, 0><<<dim3(4, 512), 256, GEMM_SMEM>>>(xw, wp, proj_b, q, 512, 512);
    ln_res_kernel<<<NTOK, 128>>>(q, x, n1g, n1b, v, xw, 1);
    mma_gemm<1, 1><<<dim3(16, 512), 256, GEMM_SMEM>>>(xw, wf1, b1, hb, 2048, 512);
    mma_gemm<0, 0><<<dim3(4, 512), 256, GEMM_SMEM>>>(hb, wf2, b2, q, 512, 2048);
    ln_res_kernel<<<NTOK, 128>>>(q, v, n2g, n2b, out, (uint32_t*)nullptr, 0);
}

// round 16
// speedup vs baseline: 1.0769x; 1.0769x over previous
#include <cuda_runtime.h>
#include <cuda_fp16.h>
#include <math.h>
#include <stdint.h>

// Problem constants
#define B_   16
#define H_   64
#define W_   64
#define C_   512
#define NH_  16
#define HD_  32
#define NTOK 65536
#define NWIN 64
#define NROW 65536

// ---------------- device scratch (allocation-free) ----------------
__device__ float g_xw[(size_t)NROW * C_];    // half activations (u32-packed), reused
__device__ float g_q [(size_t)NROW * C_];    // fp32 proj-out / fc2-out
__device__ float g_v [(size_t)NROW * C_];    // fp32 x1
__device__ float g_h [(size_t)NROW * 2048];  // qkv half (front) + mlp hidden half
__device__ float g_wr[3145728];              // fragment-packed half weights (u32 view)
__device__ float g_tbl[225 * 16];
__device__ float g_qkvb[1536];

// ---------------- helpers ----------------
__device__ __forceinline__ uint32_t smem_u32(const void* p) {
    uint32_t a;
    asm("{ .reg .u64 t; cvta.to.shared.u64 t, %1; cvt.u32.u64 %0, t; }" : "=r"(a) : "l"(p));
    return a;
}
__device__ __forceinline__ uint32_t packh2(float lo, float hi) {
    __half2 h = __floats2half2_rn(lo, hi);
    return *reinterpret_cast<uint32_t*>(&h);
}
__device__ __forceinline__ void cp16r(uint32_t saddr, const void* gsrc) {
    asm volatile("cp.async.cg.shared.global [%0], [%1], 16;" :: "r"(saddr), "l"(gsrc) : "memory");
}
#define CP_COMMIT() asm volatile("cp.async.commit_group;" ::: "memory")
#define CP_WAIT1()  asm volatile("cp.async.wait_group 1;" ::: "memory")

__device__ __forceinline__ void ldsm4(const void* p, uint32_t* r) {
    uint32_t a = smem_u32(p);
    asm volatile("ldmatrix.sync.aligned.m8n8.x4.shared.b16 {%0,%1,%2,%3}, [%4];"
        : "=r"(r[0]), "=r"(r[1]), "=r"(r[2]), "=r"(r[3]) : "r"(a));
}
__device__ __forceinline__ void mma_f16(float* c, uint32_t a0, uint32_t a1,
                                        uint32_t a2, uint32_t a3,
                                        uint32_t b0, uint32_t b1) {
    asm volatile(
        "mma.sync.aligned.m16n8k16.row.col.f32.f16.f16.f32 "
        "{%0,%1,%2,%3}, {%4,%5,%6,%7}, {%8,%9}, {%0,%1,%2,%3};"
        : "+f"(c[0]), "+f"(c[1]), "+f"(c[2]), "+f"(c[3])
        : "r"(a0), "r"(a1), "r"(a2), "r"(a3), "r"(b0), "r"(b1));
}
__device__ __forceinline__ float gelu_f(float t) {
    return 0.5f * t * (1.0f + tanhf(0.7978845608028654f * (t + 0.044715f * t * t * t)));
}

// ---------------- merged prep: weights -> fragment-packed layout ------------
// dst u32 layout [K/16][NBtot][2][32]:
//   [kp16][nb][half][lane] = half2(src[2k][c], src[2k+1][c])
//   k = kp16*8 + half*4 + (lane&3),  c = (nboff + nb)*8 + (lane>>2)
__device__ __forceinline__ void pack_frag(const float* __restrict__ src, uint32_t* __restrict__ dst,
                                          int Nsrc, int NBtot, int nboff, int local)
{
    int lane = local & 31;
    int half = (local >> 5) & 1;
    int nbc = Nsrc >> 3;
    int nb = (local >> 6) % nbc;
    int kp16 = local / (nbc << 6);
    int t = lane & 3, g = lane >> 2;
    int k2 = kp16 * 8 + half * 4 + t;           // k-pair index
    int c = nb * 8 + g;
    uint32_t v = packh2(src[(size_t)(2 * k2) * Nsrc + c],
                        src[(size_t)(2 * k2 + 1) * Nsrc + c]);
    dst[(((size_t)kp16 * NBtot + nboff + nb) * 2 + half) * 32 + lane] = v;
}

__global__ void pack_all(const float* __restrict__ q_w, const float* __restrict__ k_w,
                         const float* __restrict__ v_w, const float* __restrict__ p_w,
                         const float* __restrict__ w1, const float* __restrict__ w2,
                         const float* __restrict__ qb, const float* __restrict__ vb,
                         uint32_t* __restrict__ wqkv, uint32_t* __restrict__ wp,
                         uint32_t* __restrict__ wf1, uint32_t* __restrict__ wf2,
                         float* __restrict__ qkvb)
{
    int idx = blockIdx.x * 256 + threadIdx.x;
    // sizes (u32): 512x512 -> 131072 each; 512x2048 & 2048x512 -> 524288
    if (idx < 131072)        pack_frag(q_w, wqkv, 512, 192, 0,   idx);
    else if (idx < 262144)   pack_frag(k_w, wqkv, 512, 192, 64,  idx - 131072);
    else if (idx < 393216)   pack_frag(v_w, wqkv, 512, 192, 128, idx - 262144);
    else if (idx < 524288)   pack_frag(p_w, wp,   512, 64, 0,    idx - 393216);
    else if (idx < 1048576)  pack_frag(w1,  wf1, 2048, 256, 0,   idx - 524288);
    else if (idx < 1572864)  pack_frag(w2,  wf2,  512, 64, 0,    idx - 1048576);
    else if (idx < 1574400) {
        int i = idx - 1572864;
        float v = 0.0f;
        if (i < 512) v = qb[i];
        else if (i >= 1024) v = vb[i - 1024];
        qkvb[i] = v;
    }
}

// ---------------- fp16 mma.sync GEMM: A smem + coalesced fragment-LDG B -----
// C[M,N] = A[M,K]*B[K,N]. A: half [M][K] (u32 view). B: frag-packed.
// CTA 128x128, 8 warps (2x4 -> 64x32), K-chunk 64, 3 A-stages, 2 CTAs/SM.
#define AS_U 36                       // u32 per A smem row (32 data + 4 pad)
#define SA_U (128 * AS_U)             // 4608 u32 per stage
#define STG_U SA_U
#define STG_B (STG_U * 4)             // 18432 B
#define GEMM_SMEM (3 * STG_B)         // 55296 B
#define ARB (32 * AS_U * 4)

template<int GELU, int HALF_OUT>
__global__ void __launch_bounds__(256, 2) mma_gemm(
    const uint32_t* __restrict__ A, const uint32_t* __restrict__ B,
    const float* __restrict__ bias, void* __restrict__ Cv,
    int N, int K)
{
    extern __shared__ uint32_t smem[];
    const uint32_t sbase = smem_u32(smem);
    const int tid = threadIdx.x;
    const int wid = tid >> 5, lane = tid & 31;
    const int g = lane >> 2, t = lane & 3;
    const int lq = lane & 15, lh = lane >> 4;
    const int wm = wid >> 2, wn = wid & 3;
    const int mw = wm * 64, nw = wn * 32;
    const int m0 = blockIdx.y * 128, n0 = blockIdx.x * 128;
    const int K2 = K >> 1;
    const int NB = N >> 3;

    // A staging (pointer induction)
    const uint32_t* aptr = A + (size_t)(m0 + (tid >> 3)) * K2 + ((tid & 7) << 2);
    const size_t aRow = (size_t)32 * K2;
    const uint32_t saA = sbase + ((tid >> 3) * AS_U + ((tid & 7) << 2)) * 4;

#define STAGEA(soff) do { \
    cp16r(saA + (soff),           aptr); \
    cp16r(saA + (soff) + ARB,     aptr + aRow); \
    cp16r(saA + (soff) + 2 * ARB, aptr + 2 * aRow); \
    cp16r(saA + (soff) + 3 * ARB, aptr + 3 * aRow); \
    aptr += 32; } while (0)

    // B fragment pointer: frag-packed [K/16][NB][2][32]
    const uint32_t* bp = B + ((size_t)((n0 + nw) >> 3)) * 64 + lane;
    const size_t bKs = (size_t)NB * 64;          // next k16 step

    float acc[4][4][4];
#pragma unroll
    for (int i = 0; i < 4; i++)
#pragma unroll
        for (int j = 0; j < 4; j++)
#pragma unroll
            for (int q = 0; q < 4; q++) acc[i][j][q] = 0.0f;

    const int nch = K >> 6;

    STAGEA(0);        CP_COMMIT();
    STAGEA(STG_B);    CP_COMMIT();

    int curU = 0;
    int prevB = 2 * STG_B;

    for (int ch = 0; ch < nch; ++ch) {
        // coalesced B fragment loads for the whole chunk, before the A wait
        uint32_t bf[4][8];
#pragma unroll
        for (int ks = 0; ks < 4; ++ks) {
#pragma unroll
            for (int nf = 0; nf < 4; ++nf) {
                bf[ks][nf * 2]     = bp[nf * 64];        // half 0 -> b0
                bf[ks][nf * 2 + 1] = bp[nf * 64 + 32];   // half 1 -> b1
            }
            bp += bKs;
        }

        CP_WAIT1();
        __syncthreads();
        if (ch + 2 < nch) STAGEA(prevB);
        CP_COMMIT();

        const uint32_t* As = smem + curU;
#pragma unroll
        for (int ks = 0; ks < 4; ++ks) {
#pragma unroll
            for (int mf = 0; mf < 4; ++mf) {
                uint32_t af[4];
                ldsm4(&As[(mw + mf * 16 + lq) * AS_U + ks * 8 + (lh << 2)], af);
#pragma unroll
                for (int nf = 0; nf < 4; ++nf)
                    mma_f16(acc[mf][nf], af[0], af[1], af[2], af[3],
                            bf[ks][nf * 2], bf[ks][nf * 2 + 1]);
            }
        }

        prevB = curU * 4;
        curU = (curU == 2 * STG_U) ? 0 : curU + STG_U;
    }
#undef STAGEA

    // epilogue
#pragma unroll
    for (int mf = 0; mf < 4; ++mf) {
        const int row = m0 + mw + mf * 16 + g;
#pragma unroll
        for (int nf = 0; nf < 4; ++nf) {
            const int col = n0 + nw + nf * 8 + t * 2;
            float b0 = 0.f, b1 = 0.f;
            if (bias) { b0 = bias[col]; b1 = bias[col + 1]; }
            float c0 = acc[mf][nf][0] + b0, c1 = acc[mf][nf][1] + b1;
            float c2 = acc[mf][nf][2] + b0, c3 = acc[mf][nf][3] + b1;
            if (GELU) { c0 = gelu_f(c0); c1 = gelu_f(c1); c2 = gelu_f(c2); c3 = gelu_f(c3); }
            if (HALF_OUT) {
                uint32_t* Ch = (uint32_t*)Cv;
                Ch[((size_t)row * N + col) >> 1]       = packh2(c0, c1);
                Ch[((size_t)(row + 8) * N + col) >> 1] = packh2(c2, c3);
            } else {
                float* Cf = (float*)Cv;
                *(float2*)(Cf + (size_t)row * N + col)       = make_float2(c0, c1);
                *(float2*)(Cf + (size_t)(row + 8) * N + col) = make_float2(c2, c3);
            }
        }
    }
}

// ---------------- CPB bias table ----------------
__global__ void cpb_kernel(const float* __restrict__ w1, const float* __restrict__ b1,
                           const float* __restrict__ w2, const float* __restrict__ b2,
                           float* __restrict__ tbl)
{
    int f = blockIdx.x;
    int h = threadIdx.x;
    int i = f / 15, j = f % 15;
    float v0 = 8.0f * (float)(j - 7) / 7.0f;
    float v1 = 8.0f * (float)(i - 7) / 7.0f;
    float c0 = copysignf(log2f(fabsf(v0) + 1.0f) * (1.0f / 3.0f), v0);
    float c1 = copysignf(log2f(fabsf(v1) + 1.0f) * (1.0f / 3.0f), v1);
    float hid = fmaxf(c0 * w1[h] + c1 * w1[512 + h] + b1[h], 0.0f);

    __shared__ float red[512];
    for (int nh = 0; nh < 16; ++nh) {
        red[h] = hid * w2[h * 16 + nh];
        __syncthreads();
        for (int s = 256; s > 0; s >>= 1) {
            if (h < s) red[h] += red[h + s];
            __syncthreads();
        }
        if (h == 0) tbl[f * 16 + nh] = red[0] + b2[nh];
        __syncthreads();
    }
}

// ---------------- shift + window partition gather -> half -------------------
__global__ void gather_xw(const float* __restrict__ x, uint32_t* __restrict__ xw)
{
    size_t idx = (size_t)blockIdx.x * 256 + threadIdx.x;
    if (idx >= (size_t)NROW * 128) return;
    int c4  = (int)(idx & 127);
    int row = (int)(idx >> 7);
    int n = row & 63, bw = row >> 6;
    int win = bw & 63, b = bw >> 6;
    int wh = win >> 3, wwn = win & 7;
    int i = n >> 3, j = n & 7;
    int h = ((wh << 3) + i + 4) & 63;
    int w = ((wwn << 3) + j + 4) & 63;
    float4 vv = *(((const float4*)(x + (size_t)((b << 12) + (h << 6) + w) * C_)) + c4);
    uint2 u;
    u.x = packh2(vv.x, vv.y);
    u.y = packh2(vv.z, vv.w);
    *(uint2*)(xw + (size_t)row * 256 + c4 * 2) = u;
}

// ---------------- tensor-core windowed cosine attention ---------------------
__global__ void __launch_bounds__(128) attn_tc(
    const uint32_t* __restrict__ qkv,
    const float* __restrict__ tau, const float* __restrict__ tbl,
    uint32_t* __restrict__ out)
{
    __shared__ uint32_t Qh[64 * 17];
    __shared__ uint32_t Kh[64 * 17];
    __shared__ __half sVt[32 * 72];
    __shared__ float qn[64], kn[64];

    const int blk = blockIdx.x;
    const int head = blk & 15, bw = blk >> 4;
    const int win = bw & 63;
    const int tid = threadIdx.x;
    const int wid = tid >> 5, lane = tid & 31;
    const int g = lane >> 2, t = lane & 3;
    const int mr = wid << 4;

    const uint32_t* base = qkv + (size_t)(bw << 6) * 768 + (head << 4);

    for (int i = tid; i < 1024; i += 128) {
        int tok = i >> 4, c = i & 15;
        Qh[tok * 17 + c] = base[(size_t)tok * 768 + c];
        Kh[tok * 17 + c] = base[(size_t)tok * 768 + 256 + c];
    }
    for (int i = tid; i < 1024; i += 128) {
        int tok = i >> 4, dp = i & 15;
        uint32_t u = base[(size_t)tok * 768 + 512 + dp];
        __half2 h = *(__half2*)&u;
        sVt[(dp * 2) * 72 + tok]     = __low2half(h);
        sVt[(dp * 2 + 1) * 72 + tok] = __high2half(h);
    }
    __syncthreads();

    {
        int tok = tid & 63;
        const uint32_t* src = (tid < 64) ? &Qh[tok * 17] : &Kh[tok * 17];
        float s = 0.0f;
#pragma unroll
        for (int c = 0; c < 16; ++c) {
            float2 f = __half22float2(*(__half2*)&src[c]);
            s = fmaf(f.x, f.x, fmaf(f.y, f.y, s));
        }
        if (tid < 64) qn[tok] = sqrtf(s); else kn[tok] = sqrtf(s);
    }
    __syncthreads();

    float sacc[8][4];
#pragma unroll
    for (int nf = 0; nf < 8; ++nf)
#pragma unroll
        for (int e = 0; e < 4; ++e) sacc[nf][e] = 0.0f;

    uint32_t aq[2][4];
#pragma unroll
    for (int kb = 0; kb < 2; ++kb) {
        aq[kb][0] = Qh[(mr + g) * 17 + kb * 8 + t];
        aq[kb][1] = Qh[(mr + g + 8) * 17 + kb * 8 + t];
        aq[kb][2] = Qh[(mr + g) * 17 + kb * 8 + t + 4];
        aq[kb][3] = Qh[(mr + g + 8) * 17 + kb * 8 + t + 4];
    }
#pragma unroll
    for (int nf = 0; nf < 8; ++nf) {
        const int col = (nf << 3) + g;
#pragma unroll
        for (int kb = 0; kb < 2; ++kb) {
            uint32_t b0 = Kh[col * 17 + kb * 8 + t];
            uint32_t b1 = Kh[col * 17 + kb * 8 + t + 4];
            mma_f16(sacc[nf], aq[kb][0], aq[kb][1], aq[kb][2], aq[kb][3], b0, b1);
        }
    }

    const float ls = fmaxf(tau[head] + 2.302585092994046f, 0.01f);
    const int whb = (win >> 3) << 3, wwb = (win & 7) << 3;
    const int r1 = mr + g, r2 = mr + g + 8;
    float mx1 = -1e30f, mx2 = -1e30f;
#pragma unroll
    for (int nf = 0; nf < 8; ++nf) {
#pragma unroll
        for (int e = 0; e < 4; ++e) {
            const int r = (e < 2) ? r1 : r2;
            const int c = (nf << 3) + (t << 1) + (e & 1);
            float a = sacc[nf][e] / fmaxf(qn[r] * kn[c], 1e-6f) * ls;
            int dr = (r >> 3) - (c >> 3), dc = (r & 7) - (c & 7);
            float bsv = tbl[((dr + 7) * 15 + (dc + 7)) * 16 + head];
            a += 16.0f / (1.0f + expf(-bsv));
            int hn = whb + (r >> 3), wn = wwb + (r & 7);
            int hm = whb + (c >> 3), wm = wwb + (c & 7);
            int rn = (hn < 56 ? 0 : (hn < 60 ? 1 : 2)) * 3 + (wn < 56 ? 0 : (wn < 60 ? 1 : 2));
            int rm = (hm < 56 ? 0 : (hm < 60 ? 1 : 2)) * 3 + (wm < 56 ? 0 : (wm < 60 ? 1 : 2));
            if (rn != rm) a -= 100.0f;
            sacc[nf][e] = a;
            if (e < 2) mx1 = fmaxf(mx1, a); else mx2 = fmaxf(mx2, a);
        }
    }
#pragma unroll
    for (int o = 1; o <= 2; o <<= 1) {
        mx1 = fmaxf(mx1, __shfl_xor_sync(0xffffffffu, mx1, o));
        mx2 = fmaxf(mx2, __shfl_xor_sync(0xffffffffu, mx2, o));
    }
    float s1 = 0.0f, s2 = 0.0f;
#pragma unroll
    for (int nf = 0; nf < 8; ++nf) {
        float e0 = expf(sacc[nf][0] - mx1);
        float e1 = expf(sacc[nf][1] - mx1);
        float e2 = expf(sacc[nf][2] - mx2);
        float e3 = expf(sacc[nf][3] - mx2);
        sacc[nf][0] = e0; sacc[nf][1] = e1; sacc[nf][2] = e2; sacc[nf][3] = e3;
        s1 += e0 + e1; s2 += e2 + e3;
    }
#pragma unroll
    for (int o = 1; o <= 2; o <<= 1) {
        s1 += __shfl_xor_sync(0xffffffffu, s1, o);
        s2 += __shfl_xor_sync(0xffffffffu, s2, o);
    }
    const float inv1 = 1.0f / s1, inv2 = 1.0f / s2;

    float oacc[4][4];
#pragma unroll
    for (int nf = 0; nf < 4; ++nf)
#pragma unroll
        for (int e = 0; e < 4; ++e) oacc[nf][e] = 0.0f;

    const uint32_t* vt32 = (const uint32_t*)sVt;
#pragma unroll
    for (int kc = 0; kc < 4; ++kc) {
        uint32_t a0 = packh2(sacc[kc * 2][0],     sacc[kc * 2][1]);
        uint32_t a1 = packh2(sacc[kc * 2][2],     sacc[kc * 2][3]);
        uint32_t a2 = packh2(sacc[kc * 2 + 1][0], sacc[kc * 2 + 1][1]);
        uint32_t a3 = packh2(sacc[kc * 2 + 1][2], sacc[kc * 2 + 1][3]);
#pragma unroll
        for (int nf = 0; nf < 4; ++nf) {
            const int d = (nf << 3) + g;
            uint32_t b0 = vt32[d * 36 + kc * 8 + t];
            uint32_t b1 = vt32[d * 36 + kc * 8 + t + 4];
            mma_f16(oacc[nf], a0, a1, a2, a3, b0, b1);
        }
    }

    const size_t orow1 = (size_t)((bw << 6) + r1) * 256 + (head << 4);
    const size_t orow2 = (size_t)((bw << 6) + r2) * 256 + (head << 4);
#pragma unroll
    for (int nf = 0; nf < 4; ++nf) {
        out[orow1 + (nf << 2) + t] = packh2(oacc[nf][0] * inv1, oacc[nf][1] * inv1);
        out[orow2 + (nf << 2) + t] = packh2(oacc[nf][2] * inv2, oacc[nf][3] * inv2);
    }
}

// ---------------- (optional gather) + LayerNorm + residual ----------------
__global__ void __launch_bounds__(128) ln_res_kernel(
    const float* __restrict__ src, const float* __restrict__ resid,
    const float* __restrict__ g, const float* __restrict__ bb,
    float* __restrict__ dst, uint32_t* __restrict__ dst_half, int gather)
{
    int r = blockIdx.x, tid = threadIdx.x;
    int srow = r;
    if (gather) {
        int b = r >> 12, hw = r & 4095;
        int h = hw >> 6, w = hw & 63;
        int hh = (h + 60) & 63, wv = (w + 60) & 63;
        srow = (((b << 6) + ((hh >> 3) << 3) + (wv >> 3)) << 6) + ((hh & 7) << 3) + (wv & 7);
    }
    float4 val = ((const float4*)(src + (size_t)srow * C_))[tid];
    __shared__ float sh[4];

    float s = val.x + val.y + val.z + val.w;
#pragma unroll
    for (int o = 16; o; o >>= 1) s += __shfl_xor_sync(0xffffffffu, s, o);
    if ((tid & 31) == 0) sh[tid >> 5] = s;
    __syncthreads();
    float mean = (sh[0] + sh[1] + sh[2] + sh[3]) * (1.0f / 512.0f);
    __syncthreads();

    float dx = val.x - mean, dy = val.y - mean, dz = val.z - mean, dw = val.w - mean;
    float s2 = dx * dx + dy * dy + dz * dz + dw * dw;
#pragma unroll
    for (int o = 16; o; o >>= 1) s2 += __shfl_xor_sync(0xffffffffu, s2, o);
    if ((tid & 31) == 0) sh[tid >> 5] = s2;
    __syncthreads();
    float var = (sh[0] + sh[1] + sh[2] + sh[3]) * (1.0f / 512.0f);
    float rstd = rsqrtf(var + 1e-6f);

    float4 gg = ((const float4*)g)[tid];
    float4 bv = ((const float4*)bb)[tid];
    float4 xr = ((const float4*)(resid + (size_t)r * C_))[tid];
    float4 o;
    o.x = xr.x + dx * rstd * gg.x + bv.x;
    o.y = xr.y + dy * rstd * gg.y + bv.y;
    o.z = xr.z + dz * rstd * gg.z + bv.z;
    o.w = xr.w + dw * rstd * gg.w + bv.w;
    ((float4*)(dst + (size_t)r * C_))[tid] = o;
    if (dst_half) {
        uint2 u;
        u.x = packh2(o.x, o.y);
        u.y = packh2(o.z, o.w);
        *(uint2*)(dst_half + (size_t)r * 256 + tid * 2) = u;
    }
}

// ---------------- host launch ----------------
extern "C" void kernel_launch(void* const* d_in, const int* in_sizes, int n_in,
                              void* d_out, int out_size)
{
    const float* x      = (const float*)d_in[0];
    const float* q_w    = (const float*)d_in[1];
    const float* q_b    = (const float*)d_in[2];
    const float* k_w    = (const float*)d_in[3];
    const float* v_w    = (const float*)d_in[4];
    const float* v_b    = (const float*)d_in[5];
    const float* proj_w = (const float*)d_in[6];
    const float* proj_b = (const float*)d_in[7];
    const float* tau    = (const float*)d_in[8];
    const float* cpb_w1 = (const float*)d_in[9];
    const float* cpb_b1 = (const float*)d_in[10];
    const float* cpb_w2 = (const float*)d_in[11];
    const float* cpb_b2 = (const float*)d_in[12];
    const float* n1g    = (const float*)d_in[13];
    const float* n1b    = (const float*)d_in[14];
    const float* n2g    = (const float*)d_in[15];
    const float* n2b    = (const float*)d_in[16];
    const float* w1     = (const float*)d_in[17];
    const float* b1     = (const float*)d_in[18];
    const float* w2     = (const float*)d_in[19];
    const float* b2     = (const float*)d_in[20];
    float* out = (float*)d_out;

    float *xwf, *q, *v, *hf, *wrf, *tbl, *qkvb;
    cudaGetSymbolAddress((void**)&xwf,  g_xw);
    cudaGetSymbolAddress((void**)&q,    g_q);
    cudaGetSymbolAddress((void**)&v,    g_v);
    cudaGetSymbolAddress((void**)&hf,   g_h);
    cudaGetSymbolAddress((void**)&wrf,  g_wr);
    cudaGetSymbolAddress((void**)&tbl,  g_tbl);
    cudaGetSymbolAddress((void**)&qkvb, g_qkvb);

    uint32_t* xw   = (uint32_t*)xwf;
    uint32_t* qkvh = (uint32_t*)hf;
    uint32_t* hb   = (uint32_t*)(hf + 50331648);
    uint32_t* wr   = (uint32_t*)wrf;

    uint32_t* wqkv = wr;                 // frag-packed [32][192][2][32]
    uint32_t* wp   = wr + 393216;        // [32][64][2][32]
    uint32_t* wf1  = wr + 524288;        // [32][256][2][32]
    uint32_t* wf2  = wr + 1048576;       // [128][64][2][32]

    cudaFuncSetAttribute((const void*)mma_gemm<0, 0>,
                         cudaFuncAttributeMaxDynamicSharedMemorySize, GEMM_SMEM);
    cudaFuncSetAttribute((const void*)mma_gemm<0, 1>,
                         cudaFuncAttributeMaxDynamicSharedMemorySize, GEMM_SMEM);
    cudaFuncSetAttribute((const void*)mma_gemm<1, 1>,
                         cudaFuncAttributeMaxDynamicSharedMemorySize, GEMM_SMEM);

    pack_all<<<6150, 256>>>(q_w, k_w, v_w, proj_w, w1, w2, q_b, v_b,
                            wqkv, wp, wf1, wf2, qkvb);
    cpb_kernel<<<225, 512>>>(cpb_w1, cpb_b1, cpb_w2, cpb_b2, tbl);
    gather_xw<<<(NROW * 128) / 256, 256>>>(x, xw);

    mma_gemm<0, 1><<<dim3(12, 512), 256, GEMM_SMEM>>>(xw, wqkv, qkvb, qkvh, 1536, 512);
    attn_tc<<<16384, 128>>>(qkvh, tau, tbl, xw);
    mma_gemm<0, 0><<<dim3(4, 512), 256, GEMM_SMEM>>>(xw, wp, proj_b, q, 512, 512);
    ln_res_kernel<<<NTOK, 128>>>(q, x, n1g, n1b, v, xw, 1);
    mma_gemm<1, 1><<<dim3(16, 512), 256, GEMM_SMEM>>>(xw, wf1, b1, hb, 2048, 512);
    mma_gemm<0, 0><<<dim3(4, 512), 256, GEMM_SMEM>>>(hb, wf2, b2, q, 512, 2048);
    ln_res_kernel<<<NTOK, 128>>>(q, v, n2g, n2b, out, (uint32_t*)nullptr, 0);
}